// round 12
// baseline (speedup 1.0000x reference)
#include <cuda_runtime.h>
#include <cfloat>

#define NB    2
#define CC    256
#define HH    64
#define WW    64
#define KK    128
#define PH    7
#define PW    7

// NHWC scratch: [2, 64, 64, 256] floats = 8.4 MB
__device__ float g_xt[NB * HH * WW * CC];

// ---------------- Kernel 1: NCHW -> NHWC transpose ----------------
__global__ __launch_bounds__(256) void transpose_kernel(const float* __restrict__ x)
{
    __shared__ float tile[32][33];
    int b   = blockIdx.z;
    int hw0 = blockIdx.x * 32;
    int c0  = blockIdx.y * 32;

    const float* src = x    + (size_t)b * CC * (HH * WW);
    float*       dst = g_xt + (size_t)b * (HH * WW) * CC;

    #pragma unroll
    for (int i = 0; i < 4; ++i) {
        int c = c0 + threadIdx.y + i * 8;
        tile[threadIdx.y + i * 8][threadIdx.x] = src[(size_t)c * (HH * WW) + hw0 + threadIdx.x];
    }
    __syncthreads();
    #pragma unroll
    for (int i = 0; i < 4; ++i) {
        int hw = hw0 + threadIdx.y + i * 8;
        dst[(size_t)hw * CC + c0 + threadIdx.x] = tile[threadIdx.x][threadIdx.y + i * 8];
    }
}

// ---------------- Kernel 2: ROI max-pool, warp-per-bin, 4-row batches ----------------
// Block = (k, cg in {0,1}, bin-row i). 7 warps; warp j pools bin (i,j).
// Lane = float4 channel quad -> warp covers 128 channels; 1 LDG.128/pixel.
// Rows batched 4 at a time with clamp-duplication (clamps hoisted out of the
// w loop) -> 4 independent loads in flight per w iteration.
__global__ __launch_bounds__(224, 7) void roipool_rowbatch_kernel(
    const float* __restrict__ rois,  // [K, 5]
    float* __restrict__ out)         // [K, C, 7, 7]
{
    __shared__ float stage[128 * PW];  // [c_local][j]

    int bid = blockIdx.x;
    int k   = bid / (2 * PH);
    int rem = bid - k * (2 * PH);
    int cg  = rem / PH;          // 128-channel half
    int i   = rem - cg * PH;     // bin row
    int j    = threadIdx.x >> 5; // warp -> bin col
    int lane = threadIdx.x & 31;

    const float* r = rois + k * 5;
    int b  = (int)r[0];
    // IEEE RN multiply (0.0625 exact), round half-to-even like jnp.round
    int x1 = (int)rintf(__fmul_rn(r[1], 0.0625f));
    int y1 = (int)rintf(__fmul_rn(r[2], 0.0625f));
    int x2 = (int)rintf(__fmul_rn(r[3], 0.0625f));
    int y2 = (int)rintf(__fmul_rn(r[4], 0.0625f));

    int roi_w = max(x2 - x1 + 1, 1);
    int roi_h = max(y2 - y1 + 1, 1);

    // XLA rewrites (x / 7) -> x * RN(1/7); RN(1/7) = 0x3E124925
    const float RECIP7 = __int_as_float(0x3E124925);
    float bw = __fmul_rn((float)roi_w, RECIP7);
    float bh = __fmul_rn((float)roi_h, RECIP7);

    int hs = min(max((int)floorf(__fmul_rn((float)i,       bh)) + y1, 0), HH);
    int he = min(max((int)ceilf (__fmul_rn((float)(i + 1), bh)) + y1, 0), HH);
    int ws = min(max((int)floorf(__fmul_rn((float)j,       bw)) + x1, 0), WW);
    int we = min(max((int)ceilf (__fmul_rn((float)(j + 1), bw)) + x1, 0), WW);

    float4 acc = make_float4(0.f, 0.f, 0.f, 0.f);
    if (hs < he && ws < we) {
        acc = make_float4(-FLT_MAX, -FLT_MAX, -FLT_MAX, -FLT_MAX);
        // float4 units: pixel (h,w) at (h*WW+w)*64 + cg*32 + lane
        const float4* fb = (const float4*)(g_xt + (size_t)b * (HH * WW) * CC)
                           + cg * 32 + lane;
        int hl = he - 1;
        for (int hb = hs; hb < he; hb += 4) {
            // Row clamps hoisted out of the w loop (duplicates are no-ops under max)
            size_t o0 = (size_t)(hb                * WW) * 64;
            size_t o1 = (size_t)(min(hb + 1, hl)   * WW) * 64;
            size_t o2 = (size_t)(min(hb + 2, hl)   * WW) * 64;
            size_t o3 = (size_t)(min(hb + 3, hl)   * WW) * 64;
            for (int w = ws; w < we; ++w) {
                size_t wo = (size_t)w * 64;
                float4 v0 = __ldg(fb + o0 + wo);
                float4 v1 = __ldg(fb + o1 + wo);
                float4 v2 = __ldg(fb + o2 + wo);
                float4 v3 = __ldg(fb + o3 + wo);
                acc.x = fmaxf(fmaxf(acc.x, v0.x), fmaxf(fmaxf(v1.x, v2.x), v3.x));
                acc.y = fmaxf(fmaxf(acc.y, v0.y), fmaxf(fmaxf(v1.y, v2.y), v3.y));
                acc.z = fmaxf(fmaxf(acc.z, v0.z), fmaxf(fmaxf(v1.z, v2.z), v3.z));
                acc.w = fmaxf(fmaxf(acc.w, v0.w), fmaxf(fmaxf(v1.w, v2.w), v3.w));
            }
        }
    }

    int c0 = lane * 4;
    stage[(c0 + 0) * PW + j] = acc.x;
    stage[(c0 + 1) * PW + j] = acc.y;
    stage[(c0 + 2) * PW + j] = acc.z;
    stage[(c0 + 3) * PW + j] = acc.w;
    __syncthreads();

    // out[k, cg*128 + c, i, j]; channel stride = 49
    float* o = out + (size_t)k * (CC * PH * PW) + (size_t)cg * 128 * (PH * PW) + i * PW;
    for (int idx = threadIdx.x; idx < 128 * PW; idx += 224) {
        int c  = idx / PW;
        int jj = idx - c * PW;
        o[(size_t)c * (PH * PW) + jj] = stage[idx];
    }
}

extern "C" void kernel_launch(void* const* d_in, const int* in_sizes, int n_in,
                              void* d_out, int out_size)
{
    const float* x    = (const float*)d_in[0];
    const float* rois = (const float*)d_in[1];
    if (n_in >= 2 && in_sizes[0] < in_sizes[1]) {
        x    = (const float*)d_in[1];
        rois = (const float*)d_in[0];
    }
    float* out = (float*)d_out;

    dim3 tgrid(HH * WW / 32, CC / 32, NB);   // (128, 8, 2)
    dim3 tblk(32, 8);
    transpose_kernel<<<tgrid, tblk>>>(x);

    roipool_rowbatch_kernel<<<KK * 2 * PH, 224>>>(rois, out);  // 1792 blocks
}